// round 11
// baseline (speedup 1.0000x reference)
#include <cuda_runtime.h>
#include <math.h>
#include <stdint.h>

// ---------------------------------------------------------------------------
// FramePriorNetwork. Fixed shapes. Tensor cores via bf16 2-term split
// (hi + lo), 3 products. Flash attention. Convs AND gemms consume PRE-SPLIT
// weights (packed bf16 pairs); convs also consume pre-split activations.
// ---------------------------------------------------------------------------
#define B_   4
#define T_   800
#define H_   512
#define FF_  2048
#define NH_  8
#define NL_  6
#define HEAD_ 64
#define BHT_ (B_ * H_ * T_)
#define T2_  840                      // padded activation stride (t+1 indexing)

__device__ float g_h[BHT_];
__device__ float g_q[BHT_];
__device__ float g_k[BHT_];
__device__ float g_v[BHT_];
__device__ float g_att[BHT_];
__device__ float g_y[BHT_];
__device__ float g_rl[B_ * NH_ * T_ * 9];
__device__ float g_ff[B_ * FF_ * T_];

// pre-split conv weights: packed bf16 pairs (2 consecutive k as one u32)
#define W1P_ (NL_ * FF_ * (H_ * 3 / 2))    // 6*2048*768
#define W2P_ (NL_ * H_ * (FF_ * 3 / 2))    // 6*512*3072
__device__ uint32_t gW1hi[W1P_], gW1lo[W1P_];
__device__ uint32_t gW2hi[W2P_], gW2lo[W2P_];
// pre-split gemm weights (flat row-major pairs)
#define WQP_ (NL_ * H_ * H_ / 2)           // per q/k/v/o matrix set
#define WPP_ (2 * H_ * H_ / 2)             // final projection
__device__ uint32_t gWqh[WQP_], gWql[WQP_];
__device__ uint32_t gWkh[WQP_], gWkl[WQP_];
__device__ uint32_t gWvh[WQP_], gWvl[WQP_];
__device__ uint32_t gWoh[WQP_], gWol[WQP_];
__device__ uint32_t gWph[WPP_], gWpl[WPP_];
// pre-split activations: interleaved element = hi16 | lo16<<16, zero-padded
__device__ uint32_t gXa[B_ * H_ * T2_];    // conv1 input  (ln1 out * mask)
__device__ uint32_t gXf[B_ * FF_ * T2_];   // conv2 input  (relu(conv1)*mask)

// ---------------------------------------------------------------------------
__global__ void init_h_kernel(const float* __restrict__ x, const float* __restrict__ xm) {
    int idx = blockIdx.x * blockDim.x + threadIdx.x;
    if (idx >= BHT_) return;
    int t = idx % T_;
    int b = idx / (H_ * T_);
    g_h[idx] = x[idx] * xm[b * T_ + t];
}
__global__ void maskh_kernel(const float* __restrict__ xm) {
    int idx = blockIdx.x * blockDim.x + threadIdx.x;
    if (idx >= BHT_) return;
    int t = idx % T_;
    int b = idx / (H_ * T_);
    g_h[idx] *= xm[b * T_ + t];
}

// ---------------------------------------------------------------------------
__device__ __forceinline__ void mma_bf16(float* d, const uint32_t* a, const uint32_t* b) {
    asm volatile(
        "mma.sync.aligned.m16n8k16.row.col.f32.bf16.bf16.f32 "
        "{%0,%1,%2,%3}, {%4,%5,%6,%7}, {%8,%9}, {%0,%1,%2,%3};\n"
        : "+f"(d[0]), "+f"(d[1]), "+f"(d[2]), "+f"(d[3])
        : "r"(a[0]), "r"(a[1]), "r"(a[2]), "r"(a[3]), "r"(b[0]), "r"(b[1]));
}
__device__ __forceinline__ void split_pack(float va, float vb, uint32_t& hi, uint32_t& lo) {
    uint32_t ua = (__float_as_uint(va) + 0x8000u) & 0xffff0000u;
    uint32_t ub = (__float_as_uint(vb) + 0x8000u) & 0xffff0000u;
    float ra = va - __uint_as_float(ua);
    float rb = vb - __uint_as_float(ub);
    uint32_t la = (__float_as_uint(ra) + 0x8000u) & 0xffff0000u;
    uint32_t lb = (__float_as_uint(rb) + 0x8000u) & 0xffff0000u;
    hi = __byte_perm(ua, ub, 0x7632);
    lo = __byte_perm(la, lb, 0x7632);
}
__device__ __forceinline__ void split2_store(uint32_t* hiB, uint32_t* loB, int idx,
                                             float va, float vb) {
    uint32_t hi, lo;
    split_pack(va, vb, hi, lo);
    hiB[idx] = hi;
    loB[idx] = lo;
}
// interleaved single element: hi16 in low half, lo16 in high half
__device__ __forceinline__ uint32_t pack_elem(float v) {
    uint32_t h = (__float_as_uint(v) + 0x8000u) & 0xffff0000u;
    float r = v - __uint_as_float(h);
    uint32_t l = (__float_as_uint(r) + 0x8000u) & 0xffff0000u;
    return (h >> 16) | l;
}

// ---------------------------------------------------------------------------
__global__ void presplit_w_kernel(const float* __restrict__ W,
                                  uint32_t* __restrict__ hi, uint32_t* __restrict__ lo,
                                  int npairs) {
    int i = blockIdx.x * blockDim.x + threadIdx.x;
    if (i >= npairs) return;
    float2 w = *(const float2*)&W[2 * i];
    uint32_t h, l;
    split_pack(w.x, w.y, h, l);
    hi[i] = h;
    lo[i] = l;
}
__global__ void zero_pads_kernel() {
    int i = blockIdx.x * blockDim.x + threadIdx.x;
    const int na = B_ * H_ * T2_;
    const int nf = B_ * FF_ * T2_;
    if (i < na) gXa[i] = 0u;
    if (i < nf) gXf[i] = 0u;
}

// ---------------------------------------------------------------------------
// GEMM core with PRE-SPLIT weights: Y[m,t] = sum_k W[m,k] X[k,t] + bias[m]
__device__ __forceinline__ void gemm_core_psw(
    const uint32_t* __restrict__ Whi, const uint32_t* __restrict__ Wlo,
    const float* __restrict__ bias,
    const float* __restrict__ Xb, float* __restrict__ Yb,
    int K, int t0, int m0)
{
    __shared__ uint32_t sWhi[128 * 20], sWlo[128 * 20];
    __shared__ uint32_t sXhi[16 * 72], sXlo[16 * 72];
    const int tid  = threadIdx.x;
    const int lane = tid & 31;
    const int w    = tid >> 5;
    const int wm   = w >> 1;
    const int wn   = w & 1;
    const int lq   = lane >> 2;
    const int lr   = lane & 3;
    const int Wrow = K >> 1;            // pairs per row

    float acc[2][4][4];
#pragma unroll
    for (int i = 0; i < 2; i++)
#pragma unroll
        for (int j = 0; j < 4; j++)
#pragma unroll
            for (int r = 0; r < 4; r++) acc[i][j][r] = 0.f;

    for (int k0 = 0; k0 < K; k0 += 32) {
#pragma unroll
        for (int it = 0; it < 8; it++) {
            int idx = tid + it * 256;
            int kp = idx & 15, m = idx >> 4;
            size_t g = (size_t)(m0 + m) * Wrow + (k0 >> 1) + kp;
            sWhi[m * 20 + kp] = Whi[g];
            sWlo[m * 20 + kp] = Wlo[g];
        }
#pragma unroll
        for (int it = 0; it < 4; it++) {
            int idx = tid + it * 256;
            int t = idx & 63, kp = idx >> 6;
            int tg = t0 + t;
            float xa = 0.f, xb = 0.f;
            if (tg < T_) {
                xa = Xb[(size_t)(k0 + 2 * kp) * T_ + tg];
                xb = Xb[(size_t)(k0 + 2 * kp + 1) * T_ + tg];
            }
            split2_store(sXhi, sXlo, kp * 72 + t, xa, xb);
        }
        __syncthreads();
#pragma unroll
        for (int kh = 0; kh < 2; kh++) {
            const int kp0 = kh * 8;
            uint32_t ahi[2][4], alo[2][4];
#pragma unroll
            for (int i = 0; i < 2; i++) {
                int row = wm * 32 + i * 16 + lq;
                int c0 = kp0 + lr, c1 = kp0 + 4 + lr;
                ahi[i][0] = sWhi[row * 20 + c0];       alo[i][0] = sWlo[row * 20 + c0];
                ahi[i][1] = sWhi[(row + 8) * 20 + c0]; alo[i][1] = sWlo[(row + 8) * 20 + c0];
                ahi[i][2] = sWhi[row * 20 + c1];       alo[i][2] = sWlo[row * 20 + c1];
                ahi[i][3] = sWhi[(row + 8) * 20 + c1]; alo[i][3] = sWlo[(row + 8) * 20 + c1];
            }
#pragma unroll
            for (int j = 0; j < 4; j++) {
                int tt = wn * 32 + j * 8 + lq;
                uint32_t bhi[2], blo[2];
                bhi[0] = sXhi[(kp0 + lr) * 72 + tt];     blo[0] = sXlo[(kp0 + lr) * 72 + tt];
                bhi[1] = sXhi[(kp0 + 4 + lr) * 72 + tt]; blo[1] = sXlo[(kp0 + 4 + lr) * 72 + tt];
#pragma unroll
                for (int i = 0; i < 2; i++) {
                    mma_bf16(acc[i][j], ahi[i], bhi);
                    mma_bf16(acc[i][j], alo[i], bhi);
                    mma_bf16(acc[i][j], ahi[i], blo);
                }
            }
        }
        __syncthreads();
    }
#pragma unroll
    for (int i = 0; i < 2; i++) {
        int r0 = m0 + wm * 32 + i * 16 + lq;
        float b0 = bias[r0], b1 = bias[r0 + 8];
#pragma unroll
        for (int j = 0; j < 4; j++) {
            int t = t0 + wn * 32 + j * 8 + 2 * lr;
            if (t >= T_) continue;
            *(float2*)&Yb[(size_t)r0 * T_ + t] = make_float2(acc[i][j][0] + b0, acc[i][j][1] + b0);
            *(float2*)&Yb[(size_t)(r0 + 8) * T_ + t] = make_float2(acc[i][j][2] + b1, acc[i][j][3] + b1);
        }
    }
}

__global__ __launch_bounds__(256, 2) void gemm_tc_kernel(
    const uint32_t* __restrict__ Whi, const uint32_t* __restrict__ Wlo,
    const float* __restrict__ bias,
    const float* __restrict__ X, float* __restrict__ Y, int M, int K)
{
    const int b = blockIdx.z;
    gemm_core_psw(Whi, Wlo, bias, X + (size_t)b * K * T_, Y + (size_t)b * M * T_,
                  K, blockIdx.x * 64, blockIdx.y * 128);
}

__global__ __launch_bounds__(256, 2) void gemm3_tc_kernel(
    const uint32_t* __restrict__ Wqh, const uint32_t* __restrict__ Wql,
    const float* __restrict__ bq, float* __restrict__ Yq,
    const uint32_t* __restrict__ Wkh, const uint32_t* __restrict__ Wkl,
    const float* __restrict__ bk, float* __restrict__ Yk,
    const uint32_t* __restrict__ Wvh, const uint32_t* __restrict__ Wvl,
    const float* __restrict__ bv, float* __restrict__ Yv,
    const float* __restrict__ X)
{
    const int b = blockIdx.z;
    const int sel = blockIdx.y >> 2;
    const int m0 = (blockIdx.y & 3) * 128;
    const uint32_t* Wh = (sel == 0) ? Wqh : (sel == 1) ? Wkh : Wvh;
    const uint32_t* Wl = (sel == 0) ? Wql : (sel == 1) ? Wkl : Wvl;
    const float* bias = (sel == 0) ? bq : (sel == 1) ? bk : bv;
    float* Y = (sel == 0) ? Yq : (sel == 1) ? Yk : Yv;
    gemm_core_psw(Wh, Wl, bias, X + (size_t)b * H_ * T_, Y + (size_t)b * H_ * T_,
                  H_, blockIdx.x * 64, m0);
}

// ---------------------------------------------------------------------------
// Conv1d KS=3 pad 1, pre-split weights + pre-split padded activations.
__global__ __launch_bounds__(256, 2) void conv_tc_kernel(
    const uint32_t* __restrict__ Whi, const uint32_t* __restrict__ Wlo,
    const float* __restrict__ bias,
    const uint32_t* __restrict__ Xp,
    float* __restrict__ OutF32, uint32_t* __restrict__ OutSplit,
    const float* __restrict__ xm, int M, int C, int split_out)
{
    __shared__ uint32_t sWhi[128 * 28], sWlo[128 * 28];
    __shared__ uint32_t sXhi[24 * 72], sXlo[24 * 72];
    __shared__ float msk[66];
    const int b  = blockIdx.z;
    const int t0 = blockIdx.x * 64;
    const int m0 = blockIdx.y * 128;
    const int tid  = threadIdx.x;
    const int lane = tid & 31;
    const int w    = tid >> 5;
    const int wm   = w >> 1;
    const int wn   = w & 1;
    const int lq   = lane >> 2;
    const int lr   = lane & 3;
    const int Wrow = C * 3 / 2;

    if (tid < 66) {
        int t = t0 - 1 + tid;
        msk[tid] = (t >= 0 && t < T_) ? xm[b * T_ + t] : 0.f;
    }
    float acc[2][4][4];
#pragma unroll
    for (int i = 0; i < 2; i++)
#pragma unroll
        for (int j = 0; j < 4; j++)
#pragma unroll
            for (int r = 0; r < 4; r++) acc[i][j][r] = 0.f;

    const uint32_t* Xb = Xp + (size_t)b * C * T2_;
    __syncthreads();

    for (int c0 = 0; c0 < C; c0 += 16) {
#pragma unroll
        for (int it = 0; it < 12; it++) {
            int idx = tid + it * 256;
            int kp = idx % 24, o = idx / 24;
            size_t g = (size_t)(m0 + o) * Wrow + (c0 * 3) / 2 + kp;
            sWhi[o * 28 + kp] = Whi[g];
            sWlo[o * 28 + kp] = Wlo[g];
        }
#pragma unroll
        for (int it = 0; it < 6; it++) {
            int idx = tid + it * 256;
            int t = idx & 63, kp = idx >> 6;
            int ck0 = 2 * kp, ck1 = 2 * kp + 1;
            int ca = ck0 / 3, ka = ck0 % 3;
            int cb = ck1 / 3, kb = ck1 % 3;
            uint32_t e0 = Xb[(size_t)(c0 + ca) * T2_ + t0 + t + ka];
            uint32_t e1 = Xb[(size_t)(c0 + cb) * T2_ + t0 + t + kb];
            sXhi[kp * 72 + t] = __byte_perm(e0, e1, 0x5410);
            sXlo[kp * 72 + t] = __byte_perm(e0, e1, 0x7632);
        }
        __syncthreads();
#pragma unroll
        for (int kh = 0; kh < 3; kh++) {
            const int kp0 = kh * 8;
            uint32_t ahi[2][4], alo[2][4];
#pragma unroll
            for (int i = 0; i < 2; i++) {
                int row = wm * 32 + i * 16 + lq;
                int c0i = kp0 + lr, c1i = kp0 + 4 + lr;
                ahi[i][0] = sWhi[row * 28 + c0i];       alo[i][0] = sWlo[row * 28 + c0i];
                ahi[i][1] = sWhi[(row + 8) * 28 + c0i]; alo[i][1] = sWlo[(row + 8) * 28 + c0i];
                ahi[i][2] = sWhi[row * 28 + c1i];       alo[i][2] = sWlo[row * 28 + c1i];
                ahi[i][3] = sWhi[(row + 8) * 28 + c1i]; alo[i][3] = sWlo[(row + 8) * 28 + c1i];
            }
#pragma unroll
            for (int j = 0; j < 4; j++) {
                int tt = wn * 32 + j * 8 + lq;
                uint32_t bhi[2], blo[2];
                bhi[0] = sXhi[(kp0 + lr) * 72 + tt];     blo[0] = sXlo[(kp0 + lr) * 72 + tt];
                bhi[1] = sXhi[(kp0 + 4 + lr) * 72 + tt]; blo[1] = sXlo[(kp0 + 4 + lr) * 72 + tt];
#pragma unroll
                for (int i = 0; i < 2; i++) {
                    mma_bf16(acc[i][j], ahi[i], bhi);
                    mma_bf16(acc[i][j], alo[i], bhi);
                    mma_bf16(acc[i][j], ahi[i], blo);
                }
            }
        }
        __syncthreads();
    }
#pragma unroll
    for (int i = 0; i < 2; i++) {
        int r0 = m0 + wm * 32 + i * 16 + lq;
        float bb0 = bias[r0], bb1 = bias[r0 + 8];
#pragma unroll
        for (int j = 0; j < 4; j++) {
            int tcol = wn * 32 + j * 8 + 2 * lr;
            if (split_out) {
#pragma unroll
                for (int cc = 0; cc < 2; cc++) {
                    int t = t0 + tcol + cc;
                    if (t >= T_) continue;
                    float mk = msk[1 + tcol + cc];
                    float v0 = fmaxf(acc[i][j][cc] + bb0, 0.f) * mk;
                    float v1 = fmaxf(acc[i][j][cc + 2] + bb1, 0.f) * mk;
                    OutSplit[(size_t)((size_t)b * M + r0) * T2_ + t + 1] = pack_elem(v0);
                    OutSplit[(size_t)((size_t)b * M + r0 + 8) * T2_ + t + 1] = pack_elem(v1);
                }
            } else {
                int t = t0 + tcol;
                if (t >= T_) continue;
                float mk0 = msk[1 + tcol];
                float mk1 = msk[1 + tcol + 1];
                float v00 = (acc[i][j][0] + bb0) * mk0, v01 = (acc[i][j][1] + bb0) * mk1;
                float v10 = (acc[i][j][2] + bb1) * mk0, v11 = (acc[i][j][3] + bb1) * mk1;
                *(float2*)&OutF32[(size_t)((size_t)b * M + r0) * T_ + t] = make_float2(v00, v01);
                *(float2*)&OutF32[(size_t)((size_t)b * M + r0 + 8) * T_ + t] = make_float2(v10, v11);
            }
        }
    }
}

// ---------------------------------------------------------------------------
__global__ void relk_kernel(const float* __restrict__ ek, float scale) {
    int w = (blockIdx.x * blockDim.x + threadIdx.x) >> 5;
    int lane = threadIdx.x & 31;
    if (w >= B_ * NH_ * T_) return;
    int bh = w / T_, t = w % T_;
    const float* qb = g_q + (size_t)bh * HEAD_ * T_ + t;
    float q0 = qb[(size_t)lane * T_] * scale;
    float q1 = qb[(size_t)(lane + 32) * T_] * scale;
#pragma unroll
    for (int j = 0; j < 9; j++) {
        float v = q0 * ek[j * HEAD_ + lane] + q1 * ek[j * HEAD_ + lane + 32];
#pragma unroll
        for (int off = 16; off > 0; off >>= 1) v += __shfl_down_sync(0xffffffffu, v, off);
        if (lane == 0) g_rl[w * 9 + j] = v;
    }
}

// ---------------------------------------------------------------------------
// Fused attention (unchanged from R8/R10 winner).
__global__ __launch_bounds__(128, 3) void attn_fused_kernel(
    const float* __restrict__ xm, float scale, const float* __restrict__ ev)
{
    __shared__ uint32_t sU[9216];
    __shared__ float rlb[576];
    __shared__ float bnd[576];
    __shared__ float evs[576];
    __shared__ float sMs[64];
    __shared__ float sM[64], sL[64];

    uint32_t* sKhi = sU;
    uint32_t* sKlo = sU + 2304;
    uint32_t* sVhi = sU + 4608;
    uint32_t* sVlo = sU + 6912;

    const int bh = blockIdx.y;
    const int b  = bh >> 3;
    const int t0 = blockIdx.x * 64;
    const int tid = threadIdx.x;
    const int lane = tid & 31;
    const int wm = tid >> 5;
    const int lq = lane >> 2;
    const int lr = lane & 3;

    const float* Qb = g_q + (size_t)bh * HEAD_ * T_;
    const float* Kb = g_k + (size_t)bh * HEAD_ * T_;
    const float* Vb = g_v + (size_t)bh * HEAD_ * T_;
    float* Ob = g_att + (size_t)bh * HEAD_ * T_;

    const int tlA = wm * 16 + lq;
    const int tlB = tlA + 8;
    const int rA = t0 + tlA;
    const int rB = t0 + tlB;

    for (int i = tid; i < 576; i += 128) {
        int t = i / 9;
        rlb[i] = (t0 + t < T_) ? g_rl[((size_t)bh * T_ + t0 + t) * 9 + (i % 9)] : 0.f;
        bnd[i] = -1e30f;
        evs[i] = ev[i];
    }

    uint32_t qhi[4][4], qlo[4][4];
#pragma unroll
    for (int ks = 0; ks < 4; ks++) {
#pragma unroll
        for (int rr = 0; rr < 2; rr++) {
            int d0 = 16 * ks + 8 * rr + 2 * lr;
            float a0 = 0.f, a1 = 0.f, c0 = 0.f, c1 = 0.f;
            if (rA < T_) { a0 = Qb[(size_t)d0 * T_ + rA]; a1 = Qb[(size_t)(d0 + 1) * T_ + rA]; }
            if (rB < T_) { c0 = Qb[(size_t)d0 * T_ + rB]; c1 = Qb[(size_t)(d0 + 1) * T_ + rB]; }
            split_pack(a0, a1, qhi[ks][2 * rr], qlo[ks][2 * rr]);
            split_pack(c0, c1, qhi[ks][2 * rr + 1], qlo[ks][2 * rr + 1]);
        }
    }
    const float mtA = (rA < T_) ? xm[b * T_ + rA] : 0.f;
    const float mtB = (rB < T_) ? xm[b * T_ + rB] : 0.f;

    float oacc[8][4];
#pragma unroll
    for (int n = 0; n < 8; n++)
#pragma unroll
        for (int r = 0; r < 4; r++) oacc[n][r] = 0.f;
    float mA = -1e30f, mB = -1e30f, lA = 0.f, lB = 0.f;

    for (int s0 = 0; s0 < T_; s0 += 64) {
        __syncthreads();
#pragma unroll
        for (int it = 0; it < 16; it++) {
            int idx = tid + it * 128;
            {
                int s = idx & 63, dp = idx >> 6;
                int sg = s0 + s;
                float k0 = 0.f, k1 = 0.f;
                if (sg < T_) {
                    k0 = Kb[(size_t)(2 * dp) * T_ + sg];
                    k1 = Kb[(size_t)(2 * dp + 1) * T_ + sg];
                }
                split2_store(sKhi, sKlo, dp * 72 + s, k0, k1);
            }
            {
                int sp = idx & 31, d = idx >> 5;
                int sg = s0 + 2 * sp;
                float v0 = 0.f, v1 = 0.f;
                if (sg < T_ - 1) {
                    float2 vv = *(const float2*)&Vb[(size_t)d * T_ + sg];
                    v0 = vv.x; v1 = vv.y;
                }
                split2_store(sVhi, sVlo, d * 36 + sp, v0, v1);
            }
        }
        if (tid < 64) sMs[tid] = (s0 + tid < T_) ? xm[b * T_ + s0 + tid] : 0.f;
        __syncthreads();

        float sacc[8][4];
#pragma unroll
        for (int j = 0; j < 8; j++)
#pragma unroll
            for (int r = 0; r < 4; r++) sacc[j][r] = 0.f;
#pragma unroll
        for (int ks = 0; ks < 4; ks++) {
#pragma unroll
            for (int j = 0; j < 8; j++) {
                uint32_t bhi[2], blo[2];
                bhi[0] = sKhi[(8 * ks + lr) * 72 + 8 * j + lq];
                blo[0] = sKlo[(8 * ks + lr) * 72 + 8 * j + lq];
                bhi[1] = sKhi[(8 * ks + 4 + lr) * 72 + 8 * j + lq];
                blo[1] = sKlo[(8 * ks + 4 + lr) * 72 + 8 * j + lq];
                mma_bf16(sacc[j], qhi[ks], bhi);
                mma_bf16(sacc[j], qlo[ks], bhi);
                mma_bf16(sacc[j], qhi[ks], blo);
            }
        }

        float mxA = -1e30f, mxB = -1e30f;
#pragma unroll
        for (int j = 0; j < 8; j++) {
#pragma unroll
            for (int cc = 0; cc < 2; cc++) {
                int sl = 8 * j + 2 * lr + cc;
                int sc = s0 + sl;
                float msv = sMs[sl];
                bool colOOB = (sc >= T_);
                {
                    float v = sacc[j][cc] * scale;
                    int jj = sc - rA + 4;
                    bool inb = (jj >= 0 && jj < 9);
                    if (inb) v += rlb[tlA * 9 + jj];
                    if (mtA == 0.f || msv == 0.f) v = -10000.0f;
                    if (colOOB) v = -1e30f;
                    if (inb) bnd[tlA * 9 + jj] = v;
                    sacc[j][cc] = v;
                    mxA = fmaxf(mxA, v);
                }
                {
                    float v = sacc[j][cc + 2] * scale;
                    int jj = sc - rB + 4;
                    bool inb = (jj >= 0 && jj < 9);
                    if (inb) v += rlb[tlB * 9 + jj];
                    if (mtB == 0.f || msv == 0.f) v = -10000.0f;
                    if (colOOB) v = -1e30f;
                    if (inb) bnd[tlB * 9 + jj] = v;
                    sacc[j][cc + 2] = v;
                    mxB = fmaxf(mxB, v);
                }
            }
        }
        mxA = fmaxf(mxA, __shfl_xor_sync(0xffffffffu, mxA, 1));
        mxA = fmaxf(mxA, __shfl_xor_sync(0xffffffffu, mxA, 2));
        mxB = fmaxf(mxB, __shfl_xor_sync(0xffffffffu, mxB, 1));
        mxB = fmaxf(mxB, __shfl_xor_sync(0xffffffffu, mxB, 2));
        float mnA = fmaxf(mA, mxA), mnB = fmaxf(mB, mxB);
        float rsA = __expf(mA - mnA), rsB = __expf(mB - mnB);
        mA = mnA; mB = mnB;
        float sumA = 0.f, sumB = 0.f;
#pragma unroll
        for (int j = 0; j < 8; j++) {
            sacc[j][0] = __expf(sacc[j][0] - mnA); sumA += sacc[j][0];
            sacc[j][1] = __expf(sacc[j][1] - mnA); sumA += sacc[j][1];
            sacc[j][2] = __expf(sacc[j][2] - mnB); sumB += sacc[j][2];
            sacc[j][3] = __expf(sacc[j][3] - mnB); sumB += sacc[j][3];
        }
        sumA += __shfl_xor_sync(0xffffffffu, sumA, 1);
        sumA += __shfl_xor_sync(0xffffffffu, sumA, 2);
        sumB += __shfl_xor_sync(0xffffffffu, sumB, 1);
        sumB += __shfl_xor_sync(0xffffffffu, sumB, 2);
        lA = lA * rsA + sumA;
        lB = lB * rsB + sumB;
#pragma unroll
        for (int n = 0; n < 8; n++) {
            oacc[n][0] *= rsA; oacc[n][1] *= rsA;
            oacc[n][2] *= rsB; oacc[n][3] *= rsB;
        }

#pragma unroll
        for (int ks = 0; ks < 4; ks++) {
            uint32_t phi[4], plo[4];
            split_pack(sacc[2 * ks][0],     sacc[2 * ks][1],     phi[0], plo[0]);
            split_pack(sacc[2 * ks][2],     sacc[2 * ks][3],     phi[1], plo[1]);
            split_pack(sacc[2 * ks + 1][0], sacc[2 * ks + 1][1], phi[2], plo[2]);
            split_pack(sacc[2 * ks + 1][2], sacc[2 * ks + 1][3], phi[3], plo[3]);
#pragma unroll
            for (int n = 0; n < 8; n++) {
                uint32_t bhi[2], blo[2];
                bhi[0] = sVhi[(8 * n + lq) * 36 + 8 * ks + lr];
                blo[0] = sVlo[(8 * n + lq) * 36 + 8 * ks + lr];
                bhi[1] = sVhi[(8 * n + lq) * 36 + 8 * ks + 4 + lr];
                blo[1] = sVlo[(8 * n + lq) * 36 + 8 * ks + 4 + lr];
                mma_bf16(oacc[n], phi, bhi);
                mma_bf16(oacc[n], plo, bhi);
                mma_bf16(oacc[n], phi, blo);
            }
        }
    }

    if (lr == 0) {
        sM[tlA] = mA; sL[tlA] = lA;
        sM[tlB] = mB; sL[tlB] = lB;
    }
    __syncthreads();
    for (int i = tid; i < 576; i += 128) {
        int t = i / 9;
        bnd[i] = __expf(bnd[i] - sM[t]) / sL[t];
    }
    __syncthreads();
    float* sT = (float*)sU;
    float invA = 1.f / lA, invB = 1.f / lB;
#pragma unroll
    for (int n = 0; n < 8; n++) {
#pragma unroll
        for (int cc = 0; cc < 2; cc++) {
            int d = 8 * n + 2 * lr + cc;
            float bA = 0.f, bB = 0.f;
#pragma unroll
            for (int j = 0; j < 9; j++) {
                float e = evs[j * 64 + d];
                bA += bnd[tlA * 9 + j] * e;
                bB += bnd[tlB * 9 + j] * e;
            }
            sT[d * 65 + tlA] = oacc[n][cc] * invA + bA;
            sT[d * 65 + tlB] = oacc[n][cc + 2] * invB + bB;
        }
    }
    __syncthreads();
    for (int i = tid; i < 64 * 64; i += 128) {
        int tl = i & 63, d = i >> 6;
        int t = t0 + tl;
        if (t < T_) Ob[(size_t)d * T_ + t] = sT[d * 65 + tl];
    }
}

// ---------------------------------------------------------------------------
// LayerNorm. If xsplit != nullptr also writes split(v*mask) into padded array.
__global__ void ln_kernel(const float* __restrict__ Yadd, const float* __restrict__ g,
                          const float* __restrict__ be,
                          const float* __restrict__ xm, uint32_t* __restrict__ xsplit) {
    const int b = blockIdx.y;
    const int tx = threadIdx.x;
    const int ty = threadIdx.y;
    const int t = blockIdx.x * 32 + tx;
    __shared__ float r1[8][32], r2[8][32];
    __shared__ float mu[32], wv[32];
    float s1 = 0.f, s2 = 0.f;
    if (t < T_) {
        for (int c = ty; c < H_; c += 8) {
            size_t off = (size_t)b * H_ * T_ + (size_t)c * T_ + t;
            float v = g_h[off] + Yadd[off];
            s1 += v; s2 += v * v;
        }
    }
    r1[ty][tx] = s1; r2[ty][tx] = s2;
    __syncthreads();
    if (ty == 0) {
        float a1 = 0.f, a2 = 0.f;
#pragma unroll
        for (int i = 0; i < 8; i++) { a1 += r1[i][tx]; a2 += r2[i][tx]; }
        float m = a1 / H_;
        float var = a2 / H_ - m * m;
        mu[tx] = m;
        wv[tx] = rsqrtf(var + 1e-5f);
    }
    __syncthreads();
    if (t < T_) {
        float m = mu[tx], ww = wv[tx];
        float mk = (xsplit != nullptr) ? xm[b * T_ + t] : 0.f;
        for (int c = ty; c < H_; c += 8) {
            size_t off = (size_t)b * H_ * T_ + (size_t)c * T_ + t;
            float v = g_h[off] + Yadd[off];
            float o = (v - m) * ww * g[c] + be[c];
            g_h[off] = o;
            if (xsplit != nullptr)
                xsplit[(size_t)((size_t)b * H_ + c) * T2_ + t + 1] = pack_elem(o * mk);
        }
    }
}

// ---------------------------------------------------------------------------
__global__ void finalize_kernel(const float* __restrict__ prior, const float* __restrict__ xm,
                                float* __restrict__ out) {
    int idx = blockIdx.x * blockDim.x + threadIdx.x;
    const int total = B_ * 2 * H_ * T_;
    if (idx >= total) return;
    int t = idx % T_;
    int o = (idx / T_) % (2 * H_);
    int b = idx / (2 * H_ * T_);
    float v = prior[idx] * xm[b * T_ + t];
    size_t dst = (size_t)(o < H_ ? 0 : BHT_) + (size_t)b * H_ * T_ + (size_t)(o & (H_ - 1)) * T_ + t;
    out[dst] = v;
}

// ---------------------------------------------------------------------------
extern "C" void kernel_launch(void* const* d_in, const int* in_sizes, int n_in,
                              void* d_out, int out_size) {
    const float* x   = (const float*)d_in[0];
    const float* xm  = (const float*)d_in[1];
    const float* Wq  = (const float*)d_in[2];
    const float* bq  = (const float*)d_in[3];
    const float* Wk  = (const float*)d_in[4];
    const float* bk  = (const float*)d_in[5];
    const float* Wv  = (const float*)d_in[6];
    const float* bv  = (const float*)d_in[7];
    const float* Wo  = (const float*)d_in[8];
    const float* bo  = (const float*)d_in[9];
    const float* ek  = (const float*)d_in[10];
    const float* ev  = (const float*)d_in[11];
    const float* g1  = (const float*)d_in[12];
    const float* b1  = (const float*)d_in[13];
    const float* g2  = (const float*)d_in[14];
    const float* b2  = (const float*)d_in[15];
    const float* Wf1 = (const float*)d_in[16];
    const float* bf1 = (const float*)d_in[17];
    const float* Wf2 = (const float*)d_in[18];
    const float* bf2 = (const float*)d_in[19];
    const float* Wp  = (const float*)d_in[20];
    const float* bp  = (const float*)d_in[21];
    float* out = (float*)d_out;

    float *ph, *pq, *pk, *pv, *patt, *py, *pff;
    uint32_t *pW1h, *pW1l, *pW2h, *pW2l, *pXa, *pXf;
    uint32_t *pWqh, *pWql, *pWkh, *pWkl, *pWvh, *pWvl, *pWoh, *pWol, *pWph, *pWpl;
    cudaGetSymbolAddress((void**)&ph,  g_h);
    cudaGetSymbolAddress((void**)&pq,  g_q);
    cudaGetSymbolAddress((void**)&pk,  g_k);
    cudaGetSymbolAddress((void**)&pv,  g_v);
    cudaGetSymbolAddress((void**)&patt, g_att);
    cudaGetSymbolAddress((void**)&py,  g_y);
    cudaGetSymbolAddress((void**)&pff, g_ff);
    cudaGetSymbolAddress((void**)&pW1h, gW1hi);
    cudaGetSymbolAddress((void**)&pW1l, gW1lo);
    cudaGetSymbolAddress((void**)&pW2h, gW2hi);
    cudaGetSymbolAddress((void**)&pW2l, gW2lo);
    cudaGetSymbolAddress((void**)&pWqh, gWqh);
    cudaGetSymbolAddress((void**)&pWql, gWql);
    cudaGetSymbolAddress((void**)&pWkh, gWkh);
    cudaGetSymbolAddress((void**)&pWkl, gWkl);
    cudaGetSymbolAddress((void**)&pWvh, gWvh);
    cudaGetSymbolAddress((void**)&pWvl, gWvl);
    cudaGetSymbolAddress((void**)&pWoh, gWoh);
    cudaGetSymbolAddress((void**)&pWol, gWol);
    cudaGetSymbolAddress((void**)&pWph, gWph);
    cudaGetSymbolAddress((void**)&pWpl, gWpl);
    cudaGetSymbolAddress((void**)&pXa, gXa);
    cudaGetSymbolAddress((void**)&pXf, gXf);

    const float scale = 0.125f;
    const int TT = (T_ + 63) / 64;       // 13
    const int TB32 = (T_ + 31) / 32;     // 25

    // Prep: pre-split all weights; zero padded activation buffers.
    presplit_w_kernel<<<(W1P_ + 255) / 256, 256>>>(Wf1, pW1h, pW1l, W1P_);
    presplit_w_kernel<<<(W2P_ + 255) / 256, 256>>>(Wf2, pW2h, pW2l, W2P_);
    presplit_w_kernel<<<(WQP_ + 255) / 256, 256>>>(Wq, pWqh, pWql, WQP_);
    presplit_w_kernel<<<(WQP_ + 255) / 256, 256>>>(Wk, pWkh, pWkl, WQP_);
    presplit_w_kernel<<<(WQP_ + 255) / 256, 256>>>(Wv, pWvh, pWvl, WQP_);
    presplit_w_kernel<<<(WQP_ + 255) / 256, 256>>>(Wo, pWoh, pWol, WQP_);
    presplit_w_kernel<<<(WPP_ + 255) / 256, 256>>>(Wp, pWph, pWpl, WPP_);
    zero_pads_kernel<<<(B_ * FF_ * T2_ + 255) / 256, 256>>>();
    init_h_kernel<<<(BHT_ + 255) / 256, 256>>>(x, xm);

    const size_t WL = (size_t)H_ * H_ / 2;   // pairs per layer per matrix

    for (int L = 0; L < NL_; L++) {
        const float* ekL = ek + (size_t)L * 9 * HEAD_;
        const float* evL = ev + (size_t)L * 9 * HEAD_;

        gemm3_tc_kernel<<<dim3(TT, 12, B_), 256>>>(
            pWqh + L * WL, pWql + L * WL, bq + L * H_, pq,
            pWkh + L * WL, pWkl + L * WL, bk + L * H_, pk,
            pWvh + L * WL, pWvl + L * WL, bv + L * H_, pv, ph);

        relk_kernel<<<(B_ * NH_ * T_ * 32 + 127) / 128, 128>>>(ekL, scale);
        attn_fused_kernel<<<dim3(TT, B_ * NH_), 128>>>(xm, scale, evL);

        gemm_tc_kernel<<<dim3(TT, H_ / 128, B_), 256>>>(
            pWoh + L * WL, pWol + L * WL, bo + L * H_, patt, pq, H_, H_);
        ln_kernel<<<dim3(TB32, B_), dim3(32, 8)>>>(pq, g1 + L * H_, b1 + L * H_, xm, pXa);

        conv_tc_kernel<<<dim3(TT, FF_ / 128, B_), 256>>>(
            pW1h + (size_t)L * FF_ * (H_ * 3 / 2), pW1l + (size_t)L * FF_ * (H_ * 3 / 2),
            bf1 + L * FF_, pXa, nullptr, pXf, xm, FF_, H_, 1);
        conv_tc_kernel<<<dim3(TT, H_ / 128, B_), 256>>>(
            pW2h + (size_t)L * H_ * (FF_ * 3 / 2), pW2l + (size_t)L * H_ * (FF_ * 3 / 2),
            bf2 + L * H_, pXf, py, nullptr, xm, H_, FF_, 0);
        ln_kernel<<<dim3(TB32, B_), dim3(32, 8)>>>(py, g2 + L * H_, b2 + L * H_, xm, nullptr);
    }

    maskh_kernel<<<(BHT_ + 255) / 256, 256>>>(xm);
    gemm_tc_kernel<<<dim3(TT, 2 * H_ / 128, B_), 256>>>(pWph, pWpl, bp, ph, pff, 2 * H_, H_);
    finalize_kernel<<<(B_ * 2 * H_ * T_ + 255) / 256, 256>>>(pff, xm, out);
}

// round 13
// speedup vs baseline: 1.0560x; 1.0560x over previous
#include <cuda_runtime.h>
#include <math.h>
#include <stdint.h>

// ---------------------------------------------------------------------------
// FramePriorNetwork. bf16 2-term split tensor-core math, flash attention,
// pre-split weights/activations. GEMM + conv use a 2-stage cp.async pipeline
// with double-buffered dynamic shared memory (1 barrier per k-block).
// ---------------------------------------------------------------------------
#define B_   4
#define T_   800
#define H_   512
#define FF_  2048
#define NH_  8
#define NL_  6
#define HEAD_ 64
#define BHT_ (B_ * H_ * T_)
#define T2_  840

__device__ float g_h[BHT_];
__device__ float g_q[BHT_];
__device__ float g_k[BHT_];
__device__ float g_v[BHT_];
__device__ float g_att[BHT_];
__device__ float g_y[BHT_];
__device__ float g_rl[B_ * NH_ * T_ * 9];
__device__ float g_ff[B_ * FF_ * T_];

#define W1P_ (NL_ * FF_ * (H_ * 3 / 2))
#define W2P_ (NL_ * H_ * (FF_ * 3 / 2))
__device__ uint32_t gW1hi[W1P_], gW1lo[W1P_];
__device__ uint32_t gW2hi[W2P_], gW2lo[W2P_];
#define WQP_ (NL_ * H_ * H_ / 2)
#define WPP_ (2 * H_ * H_ / 2)
__device__ uint32_t gWqh[WQP_], gWql[WQP_];
__device__ uint32_t gWkh[WQP_], gWkl[WQP_];
__device__ uint32_t gWvh[WQP_], gWvl[WQP_];
__device__ uint32_t gWoh[WQP_], gWol[WQP_];
__device__ uint32_t gWph[WPP_], gWpl[WPP_];
__device__ uint32_t gXa[B_ * H_ * T2_];
__device__ uint32_t gXf[B_ * FF_ * T2_];

// ---------------------------------------------------------------------------
__global__ void init_h_kernel(const float* __restrict__ x, const float* __restrict__ xm) {
    int idx = blockIdx.x * blockDim.x + threadIdx.x;
    if (idx >= BHT_) return;
    int t = idx % T_;
    int b = idx / (H_ * T_);
    g_h[idx] = x[idx] * xm[b * T_ + t];
}
__global__ void maskh_kernel(const float* __restrict__ xm) {
    int idx = blockIdx.x * blockDim.x + threadIdx.x;
    if (idx >= BHT_) return;
    int t = idx % T_;
    int b = idx / (H_ * T_);
    g_h[idx] *= xm[b * T_ + t];
}

// ---------------------------------------------------------------------------
__device__ __forceinline__ void mma_bf16(float* d, const uint32_t* a, const uint32_t* b) {
    asm volatile(
        "mma.sync.aligned.m16n8k16.row.col.f32.bf16.bf16.f32 "
        "{%0,%1,%2,%3}, {%4,%5,%6,%7}, {%8,%9}, {%0,%1,%2,%3};\n"
        : "+f"(d[0]), "+f"(d[1]), "+f"(d[2]), "+f"(d[3])
        : "r"(a[0]), "r"(a[1]), "r"(a[2]), "r"(a[3]), "r"(b[0]), "r"(b[1]));
}
__device__ __forceinline__ void split_pack(float va, float vb, uint32_t& hi, uint32_t& lo) {
    uint32_t ua = (__float_as_uint(va) + 0x8000u) & 0xffff0000u;
    uint32_t ub = (__float_as_uint(vb) + 0x8000u) & 0xffff0000u;
    float ra = va - __uint_as_float(ua);
    float rb = vb - __uint_as_float(ub);
    uint32_t la = (__float_as_uint(ra) + 0x8000u) & 0xffff0000u;
    uint32_t lb = (__float_as_uint(rb) + 0x8000u) & 0xffff0000u;
    hi = __byte_perm(ua, ub, 0x7632);
    lo = __byte_perm(la, lb, 0x7632);
}
__device__ __forceinline__ void split2_store(uint32_t* hiB, uint32_t* loB, int idx,
                                             float va, float vb) {
    uint32_t hi, lo;
    split_pack(va, vb, hi, lo);
    hiB[idx] = hi;
    loB[idx] = lo;
}
__device__ __forceinline__ uint32_t pack_elem(float v) {
    uint32_t h = (__float_as_uint(v) + 0x8000u) & 0xffff0000u;
    float r = v - __uint_as_float(h);
    uint32_t l = (__float_as_uint(r) + 0x8000u) & 0xffff0000u;
    return (h >> 16) | l;
}
// cp.async 16B helper
__device__ __forceinline__ void cp16(uint32_t* sdst, const uint32_t* gsrc) {
    uint32_t sa = (uint32_t)__cvta_generic_to_shared(sdst);
    asm volatile("cp.async.cg.shared.global [%0], [%1], 16;" :: "r"(sa), "l"(gsrc));
}
#define CP_COMMIT() asm volatile("cp.async.commit_group;")
#define CP_WAIT()   asm volatile("cp.async.wait_group 0;")

// ---------------------------------------------------------------------------
__global__ void presplit_w_kernel(const float* __restrict__ W,
                                  uint32_t* __restrict__ hi, uint32_t* __restrict__ lo,
                                  int npairs) {
    int i = blockIdx.x * blockDim.x + threadIdx.x;
    if (i >= npairs) return;
    float2 w = *(const float2*)&W[2 * i];
    uint32_t h, l;
    split_pack(w.x, w.y, h, l);
    hi[i] = h;
    lo[i] = l;
}
__global__ void zero_pads_kernel() {
    int i = blockIdx.x * blockDim.x + threadIdx.x;
    const int na = B_ * H_ * T2_;
    const int nf = B_ * FF_ * T2_;
    if (i < na) gXa[i] = 0u;
    if (i < nf) gXf[i] = 0u;
}

// ---------------------------------------------------------------------------
// Pipelined GEMM core. Stage layout (u32): Whi[2560] Wlo[2560] Xhi[1152] Xlo[1152]
#define G_STG  7424
#define GEMM_DSM (2 * G_STG * 4)
__device__ __forceinline__ void gemm_core_pipe(
    const uint32_t* __restrict__ Whi, const uint32_t* __restrict__ Wlo,
    const float* __restrict__ bias,
    const float* __restrict__ Xb, float* __restrict__ Yb,
    int K, int t0, int m0)
{
    extern __shared__ uint32_t dsm[];
    const int tid  = threadIdx.x;
    const int lane = tid & 31;
    const int w    = tid >> 5;
    const int wm   = w >> 1;
    const int wn   = w & 1;
    const int lq   = lane >> 2;
    const int lr   = lane & 3;
    const int Wrow = K >> 1;
    const int nkb  = K >> 5;

    float acc[2][4][4];
#pragma unroll
    for (int i = 0; i < 2; i++)
#pragma unroll
        for (int j = 0; j < 4; j++)
#pragma unroll
            for (int r = 0; r < 4; r++) acc[i][j][r] = 0.f;

    uint32_t xh[4], xl[4];

    // ---- prologue: stage 0
    {
        uint32_t* st = dsm;
#pragma unroll
        for (int it = 0; it < 2; it++) {
            int idx = tid + it * 256;
            int row = idx >> 2, ch = idx & 3;
            cp16(st + row * 20 + ch * 4, Whi + (size_t)(m0 + row) * Wrow + ch * 4);
            cp16(st + 2560 + row * 20 + ch * 4, Wlo + (size_t)(m0 + row) * Wrow + ch * 4);
        }
#pragma unroll
        for (int it = 0; it < 4; it++) {
            int idx = tid + it * 256;
            int t = idx & 63, kp = idx >> 6;
            int tg = t0 + t;
            float xa = 0.f, xb = 0.f;
            if (tg < T_) {
                xa = Xb[(size_t)(2 * kp) * T_ + tg];
                xb = Xb[(size_t)(2 * kp + 1) * T_ + tg];
            }
            split_pack(xa, xb, xh[it], xl[it]);
        }
        CP_COMMIT();
#pragma unroll
        for (int it = 0; it < 4; it++) {
            int idx = tid + it * 256;
            int t = idx & 63, kp = idx >> 6;
            st[5120 + kp * 72 + t] = xh[it];
            st[6272 + kp * 72 + t] = xl[it];
        }
        CP_WAIT();
        __syncthreads();
    }

    for (int kb = 0; kb < nkb; kb++) {
        uint32_t* cur = dsm + (kb & 1) * G_STG;
        uint32_t* nxt = dsm + ((kb + 1) & 1) * G_STG;
        const bool more = (kb + 1 < nkb);
        if (more) {
            int kq = (kb + 1) << 4;
#pragma unroll
            for (int it = 0; it < 2; it++) {
                int idx = tid + it * 256;
                int row = idx >> 2, ch = idx & 3;
                cp16(nxt + row * 20 + ch * 4, Whi + (size_t)(m0 + row) * Wrow + kq + ch * 4);
                cp16(nxt + 2560 + row * 20 + ch * 4, Wlo + (size_t)(m0 + row) * Wrow + kq + ch * 4);
            }
            int k0n = (kb + 1) << 5;
#pragma unroll
            for (int it = 0; it < 4; it++) {
                int idx = tid + it * 256;
                int t = idx & 63, kp = idx >> 6;
                int tg = t0 + t;
                float xa = 0.f, xb = 0.f;
                if (tg < T_) {
                    xa = Xb[(size_t)(k0n + 2 * kp) * T_ + tg];
                    xb = Xb[(size_t)(k0n + 2 * kp + 1) * T_ + tg];
                }
                split_pack(xa, xb, xh[it], xl[it]);
            }
            CP_COMMIT();
        }
        const uint32_t* sWhi = cur;
        const uint32_t* sWlo = cur + 2560;
        const uint32_t* sXhi = cur + 5120;
        const uint32_t* sXlo = cur + 6272;
#pragma unroll
        for (int kh = 0; kh < 2; kh++) {
            const int kp0 = kh * 8;
            uint32_t ahi[2][4], alo[2][4];
#pragma unroll
            for (int i = 0; i < 2; i++) {
                int row = wm * 32 + i * 16 + lq;
                int c0 = kp0 + lr, c1 = kp0 + 4 + lr;
                ahi[i][0] = sWhi[row * 20 + c0];       alo[i][0] = sWlo[row * 20 + c0];
                ahi[i][1] = sWhi[(row + 8) * 20 + c0]; alo[i][1] = sWlo[(row + 8) * 20 + c0];
                ahi[i][2] = sWhi[row * 20 + c1];       alo[i][2] = sWlo[row * 20 + c1];
                ahi[i][3] = sWhi[(row + 8) * 20 + c1]; alo[i][3] = sWlo[(row + 8) * 20 + c1];
            }
#pragma unroll
            for (int j = 0; j < 4; j++) {
                int tt = wn * 32 + j * 8 + lq;
                uint32_t bhi[2], blo[2];
                bhi[0] = sXhi[(kp0 + lr) * 72 + tt];     blo[0] = sXlo[(kp0 + lr) * 72 + tt];
                bhi[1] = sXhi[(kp0 + 4 + lr) * 72 + tt]; blo[1] = sXlo[(kp0 + 4 + lr) * 72 + tt];
#pragma unroll
                for (int i = 0; i < 2; i++) {
                    mma_bf16(acc[i][j], ahi[i], bhi);
                    mma_bf16(acc[i][j], alo[i], bhi);
                    mma_bf16(acc[i][j], ahi[i], blo);
                }
            }
        }
        if (more) {
#pragma unroll
            for (int it = 0; it < 4; it++) {
                int idx = tid + it * 256;
                int t = idx & 63, kp = idx >> 6;
                nxt[5120 + kp * 72 + t] = xh[it];
                nxt[6272 + kp * 72 + t] = xl[it];
            }
        }
        CP_WAIT();
        __syncthreads();
    }
#pragma unroll
    for (int i = 0; i < 2; i++) {
        int r0 = m0 + wm * 32 + i * 16 + lq;
        float b0 = bias[r0], b1 = bias[r0 + 8];
#pragma unroll
        for (int j = 0; j < 4; j++) {
            int t = t0 + wn * 32 + j * 8 + 2 * lr;
            if (t >= T_) continue;
            *(float2*)&Yb[(size_t)r0 * T_ + t] = make_float2(acc[i][j][0] + b0, acc[i][j][1] + b0);
            *(float2*)&Yb[(size_t)(r0 + 8) * T_ + t] = make_float2(acc[i][j][2] + b1, acc[i][j][3] + b1);
        }
    }
}

__global__ __launch_bounds__(256, 2) void gemm_tc_kernel(
    const uint32_t* __restrict__ Whi, const uint32_t* __restrict__ Wlo,
    const float* __restrict__ bias,
    const float* __restrict__ X, float* __restrict__ Y, int M, int K)
{
    const int b = blockIdx.z;
    gemm_core_pipe(Whi, Wlo, bias, X + (size_t)b * K * T_, Y + (size_t)b * M * T_,
                   K, blockIdx.x * 64, blockIdx.y * 128);
}

__global__ __launch_bounds__(256, 2) void gemm3_tc_kernel(
    const uint32_t* __restrict__ Wqh, const uint32_t* __restrict__ Wql,
    const float* __restrict__ bq, float* __restrict__ Yq,
    const uint32_t* __restrict__ Wkh, const uint32_t* __restrict__ Wkl,
    const float* __restrict__ bk, float* __restrict__ Yk,
    const uint32_t* __restrict__ Wvh, const uint32_t* __restrict__ Wvl,
    const float* __restrict__ bv, float* __restrict__ Yv,
    const float* __restrict__ X)
{
    const int b = blockIdx.z;
    const int sel = blockIdx.y >> 2;
    const int m0 = (blockIdx.y & 3) * 128;
    const uint32_t* Wh = (sel == 0) ? Wqh : (sel == 1) ? Wkh : Wvh;
    const uint32_t* Wl = (sel == 0) ? Wql : (sel == 1) ? Wkl : Wvl;
    const float* bias = (sel == 0) ? bq : (sel == 1) ? bk : bv;
    float* Y = (sel == 0) ? Yq : (sel == 1) ? Yk : Yv;
    gemm_core_pipe(Wh, Wl, bias, X + (size_t)b * H_ * T_, Y + (size_t)b * H_ * T_,
                   H_, blockIdx.x * 64, m0);
}

// ---------------------------------------------------------------------------
// Pipelined conv. Stage (u32): Whi[3584] Wlo[3584] Xhi[1728] Xlo[1728] = 10624
#define C_STG  10624
#define CONV_DSM (2 * C_STG * 4)
__global__ __launch_bounds__(256, 2) void conv_tc_kernel(
    const uint32_t* __restrict__ Whi, const uint32_t* __restrict__ Wlo,
    const float* __restrict__ bias,
    const uint32_t* __restrict__ Xp,
    float* __restrict__ OutF32, uint32_t* __restrict__ OutSplit,
    const float* __restrict__ xm, int M, int C, int split_out)
{
    extern __shared__ uint32_t dsm[];
    __shared__ float msk[66];
    const int b  = blockIdx.z;
    const int t0 = blockIdx.x * 64;
    const int m0 = blockIdx.y * 128;
    const int tid  = threadIdx.x;
    const int lane = tid & 31;
    const int w    = tid >> 5;
    const int wm   = w >> 1;
    const int wn   = w & 1;
    const int lq   = lane >> 2;
    const int lr   = lane & 3;
    const int Wrow = C * 3 / 2;
    const int ncb  = C >> 4;

    if (tid < 66) {
        int t = t0 - 1 + tid;
        msk[tid] = (t >= 0 && t < T_) ? xm[b * T_ + t] : 0.f;
    }
    float acc[2][4][4];
#pragma unroll
    for (int i = 0; i < 2; i++)
#pragma unroll
        for (int j = 0; j < 4; j++)
#pragma unroll
            for (int r = 0; r < 4; r++) acc[i][j][r] = 0.f;

    const uint32_t* Xb = Xp + (size_t)b * C * T2_;
    uint32_t xh[6], xl[6];

    // prologue stage 0 (c0 = 0)
    {
        uint32_t* st = dsm;
#pragma unroll
        for (int it = 0; it < 3; it++) {
            int idx = tid + it * 256;
            int row = idx / 6, ch = idx % 6;
            cp16(st + row * 28 + ch * 4, Whi + (size_t)(m0 + row) * Wrow + ch * 4);
            cp16(st + 3584 + row * 28 + ch * 4, Wlo + (size_t)(m0 + row) * Wrow + ch * 4);
        }
#pragma unroll
        for (int it = 0; it < 6; it++) {
            int idx = tid + it * 256;
            int t = idx & 63, kp = idx >> 6;
            int ck0 = 2 * kp, ck1 = 2 * kp + 1;
            uint32_t e0 = Xb[(size_t)(ck0 / 3) * T2_ + t0 + t + ck0 % 3];
            uint32_t e1 = Xb[(size_t)(ck1 / 3) * T2_ + t0 + t + ck1 % 3];
            xh[it] = __byte_perm(e0, e1, 0x5410);
            xl[it] = __byte_perm(e0, e1, 0x7632);
        }
        CP_COMMIT();
#pragma unroll
        for (int it = 0; it < 6; it++) {
            int idx = tid + it * 256;
            int t = idx & 63, kp = idx >> 6;
            st[7168 + kp * 72 + t] = xh[it];
            st[8896 + kp * 72 + t] = xl[it];
        }
        CP_WAIT();
        __syncthreads();
    }

    for (int cb = 0; cb < ncb; cb++) {
        uint32_t* cur = dsm + (cb & 1) * C_STG;
        uint32_t* nxt = dsm + ((cb + 1) & 1) * C_STG;
        const bool more = (cb + 1 < ncb);
        if (more) {
            int wq = (cb + 1) * 24;
            int c0n = (cb + 1) << 4;
#pragma unroll
            for (int it = 0; it < 3; it++) {
                int idx = tid + it * 256;
                int row = idx / 6, ch = idx % 6;
                cp16(nxt + row * 28 + ch * 4, Whi + (size_t)(m0 + row) * Wrow + wq + ch * 4);
                cp16(nxt + 3584 + row * 28 + ch * 4, Wlo + (size_t)(m0 + row) * Wrow + wq + ch * 4);
            }
#pragma unroll
            for (int it = 0; it < 6; it++) {
                int idx = tid + it * 256;
                int t = idx & 63, kp = idx >> 6;
                int ck0 = 2 * kp, ck1 = 2 * kp + 1;
                uint32_t e0 = Xb[(size_t)(c0n + ck0 / 3) * T2_ + t0 + t + ck0 % 3];
                uint32_t e1 = Xb[(size_t)(c0n + ck1 / 3) * T2_ + t0 + t + ck1 % 3];
                xh[it] = __byte_perm(e0, e1, 0x5410);
                xl[it] = __byte_perm(e0, e1, 0x7632);
            }
            CP_COMMIT();
        }
        const uint32_t* sWhi = cur;
        const uint32_t* sWlo = cur + 3584;
        const uint32_t* sXhi = cur + 7168;
        const uint32_t* sXlo = cur + 8896;
#pragma unroll
        for (int kh = 0; kh < 3; kh++) {
            const int kp0 = kh * 8;
            uint32_t ahi[2][4], alo[2][4];
#pragma unroll
            for (int i = 0; i < 2; i++) {
                int row = wm * 32 + i * 16 + lq;
                int c0i = kp0 + lr, c1i = kp0 + 4 + lr;
                ahi[i][0] = sWhi[row * 28 + c0i];       alo[i][0] = sWlo[row * 28 + c0i];
                ahi[i][1] = sWhi[(row + 8) * 28 + c0i]; alo[i][1] = sWlo[(row + 8) * 28 + c0i];
                ahi[i][2] = sWhi[row * 28 + c1i];       alo[i][2] = sWlo[row * 28 + c1i];
                ahi[i][3] = sWhi[(row + 8) * 28 + c1i]; alo[i][3] = sWlo[(row + 8) * 28 + c1i];
            }
#pragma unroll
            for (int j = 0; j < 4; j++) {
                int tt = wn * 32 + j * 8 + lq;
                uint32_t bhi[2], blo[2];
                bhi[0] = sXhi[(kp0 + lr) * 72 + tt];     blo[0] = sXlo[(kp0 + lr) * 72 + tt];
                bhi[1] = sXhi[(kp0 + 4 + lr) * 72 + tt]; blo[1] = sXlo[(kp0 + 4 + lr) * 72 + tt];
#pragma unroll
                for (int i = 0; i < 2; i++) {
                    mma_bf16(acc[i][j], ahi[i], bhi);
                    mma_bf16(acc[i][j], alo[i], bhi);
                    mma_bf16(acc[i][j], ahi[i], blo);
                }
            }
        }
        if (more) {
#pragma unroll
            for (int it = 0; it < 6; it++) {
                int idx = tid + it * 256;
                int t = idx & 63, kp = idx >> 6;
                nxt[7168 + kp * 72 + t] = xh[it];
                nxt[8896 + kp * 72 + t] = xl[it];
            }
        }
        CP_WAIT();
        __syncthreads();
    }
#pragma unroll
    for (int i = 0; i < 2; i++) {
        int r0 = m0 + wm * 32 + i * 16 + lq;
        float bb0 = bias[r0], bb1 = bias[r0 + 8];
#pragma unroll
        for (int j = 0; j < 4; j++) {
            int tcol = wn * 32 + j * 8 + 2 * lr;
            if (split_out) {
#pragma unroll
                for (int cc = 0; cc < 2; cc++) {
                    int t = t0 + tcol + cc;
                    if (t >= T_) continue;
                    float mk = msk[1 + tcol + cc];
                    float v0 = fmaxf(acc[i][j][cc] + bb0, 0.f) * mk;
                    float v1 = fmaxf(acc[i][j][cc + 2] + bb1, 0.f) * mk;
                    OutSplit[(size_t)((size_t)b * M + r0) * T2_ + t + 1] = pack_elem(v0);
                    OutSplit[(size_t)((size_t)b * M + r0 + 8) * T2_ + t + 1] = pack_elem(v1);
                }
            } else {
                int t = t0 + tcol;
                if (t >= T_) continue;
                float mk0 = msk[1 + tcol];
                float mk1 = msk[1 + tcol + 1];
                float v00 = (acc[i][j][0] + bb0) * mk0, v01 = (acc[i][j][1] + bb0) * mk1;
                float v10 = (acc[i][j][2] + bb1) * mk0, v11 = (acc[i][j][3] + bb1) * mk1;
                *(float2*)&OutF32[(size_t)((size_t)b * M + r0) * T_ + t] = make_float2(v00, v01);
                *(float2*)&OutF32[(size_t)((size_t)b * M + r0 + 8) * T_ + t] = make_float2(v10, v11);
            }
        }
    }
}

// ---------------------------------------------------------------------------
__global__ void relk_kernel(const float* __restrict__ ek, float scale) {
    int w = (blockIdx.x * blockDim.x + threadIdx.x) >> 5;
    int lane = threadIdx.x & 31;
    if (w >= B_ * NH_ * T_) return;
    int bh = w / T_, t = w % T_;
    const float* qb = g_q + (size_t)bh * HEAD_ * T_ + t;
    float q0 = qb[(size_t)lane * T_] * scale;
    float q1 = qb[(size_t)(lane + 32) * T_] * scale;
#pragma unroll
    for (int j = 0; j < 9; j++) {
        float v = q0 * ek[j * HEAD_ + lane] + q1 * ek[j * HEAD_ + lane + 32];
#pragma unroll
        for (int off = 16; off > 0; off >>= 1) v += __shfl_down_sync(0xffffffffu, v, off);
        if (lane == 0) g_rl[w * 9 + j] = v;
    }
}

// ---------------------------------------------------------------------------
// Fused attention (R8/R10 winner, unchanged).
__global__ __launch_bounds__(128, 3) void attn_fused_kernel(
    const float* __restrict__ xm, float scale, const float* __restrict__ ev)
{
    __shared__ uint32_t sU[9216];
    __shared__ float rlb[576];
    __shared__ float bnd[576];
    __shared__ float evs[576];
    __shared__ float sMs[64];
    __shared__ float sM[64], sL[64];

    uint32_t* sKhi = sU;
    uint32_t* sKlo = sU + 2304;
    uint32_t* sVhi = sU + 4608;
    uint32_t* sVlo = sU + 6912;

    const int bh = blockIdx.y;
    const int b  = bh >> 3;
    const int t0 = blockIdx.x * 64;
    const int tid = threadIdx.x;
    const int lane = tid & 31;
    const int wm = tid >> 5;
    const int lq = lane >> 2;
    const int lr = lane & 3;

    const float* Qb = g_q + (size_t)bh * HEAD_ * T_;
    const float* Kb = g_k + (size_t)bh * HEAD_ * T_;
    const float* Vb = g_v + (size_t)bh * HEAD_ * T_;
    float* Ob = g_att + (size_t)bh * HEAD_ * T_;

    const int tlA = wm * 16 + lq;
    const int tlB = tlA + 8;
    const int rA = t0 + tlA;
    const int rB = t0 + tlB;

    for (int i = tid; i < 576; i += 128) {
        int t = i / 9;
        rlb[i] = (t0 + t < T_) ? g_rl[((size_t)bh * T_ + t0 + t) * 9 + (i % 9)] : 0.f;
        bnd[i] = -1e30f;
        evs[i] = ev[i];
    }

    uint32_t qhi[4][4], qlo[4][4];
#pragma unroll
    for (int ks = 0; ks < 4; ks++) {
#pragma unroll
        for (int rr = 0; rr < 2; rr++) {
            int d0 = 16 * ks + 8 * rr + 2 * lr;
            float a0 = 0.f, a1 = 0.f, c0 = 0.f, c1 = 0.f;
            if (rA < T_) { a0 = Qb[(size_t)d0 * T_ + rA]; a1 = Qb[(size_t)(d0 + 1) * T_ + rA]; }
            if (rB < T_) { c0 = Qb[(size_t)d0 * T_ + rB]; c1 = Qb[(size_t)(d0 + 1) * T_ + rB]; }
            split_pack(a0, a1, qhi[ks][2 * rr], qlo[ks][2 * rr]);
            split_pack(c0, c1, qhi[ks][2 * rr + 1], qlo[ks][2 * rr + 1]);
        }
    }
    const float mtA = (rA < T_) ? xm[b * T_ + rA] : 0.f;
    const float mtB = (rB < T_) ? xm[b * T_ + rB] : 0.f;

    float oacc[8][4];
#pragma unroll
    for (int n = 0; n < 8; n++)
#pragma unroll
        for (int r = 0; r < 4; r++) oacc[n][r] = 0.f;
    float mA = -1e30f, mB = -1e30f, lA = 0.f, lB = 0.f;

    for (int s0 = 0; s0 < T_; s0 += 64) {
        __syncthreads();
#pragma unroll
        for (int it = 0; it < 16; it++) {
            int idx = tid + it * 128;
            {
                int s = idx & 63, dp = idx >> 6;
                int sg = s0 + s;
                float k0 = 0.f, k1 = 0.f;
                if (sg < T_) {
                    k0 = Kb[(size_t)(2 * dp) * T_ + sg];
                    k1 = Kb[(size_t)(2 * dp + 1) * T_ + sg];
                }
                split2_store(sKhi, sKlo, dp * 72 + s, k0, k1);
            }
            {
                int sp = idx & 31, d = idx >> 5;
                int sg = s0 + 2 * sp;
                float v0 = 0.f, v1 = 0.f;
                if (sg < T_ - 1) {
                    float2 vv = *(const float2*)&Vb[(size_t)d * T_ + sg];
                    v0 = vv.x; v1 = vv.y;
                }
                split2_store(sVhi, sVlo, d * 36 + sp, v0, v1);
            }
        }
        if (tid < 64) sMs[tid] = (s0 + tid < T_) ? xm[b * T_ + s0 + tid] : 0.f;
        __syncthreads();

        float sacc[8][4];
#pragma unroll
        for (int j = 0; j < 8; j++)
#pragma unroll
            for (int r = 0; r < 4; r++) sacc[j][r] = 0.f;
#pragma unroll
        for (int ks = 0; ks < 4; ks++) {
#pragma unroll
            for (int j = 0; j < 8; j++) {
                uint32_t bhi[2], blo[2];
                bhi[0] = sKhi[(8 * ks + lr) * 72 + 8 * j + lq];
                blo[0] = sKlo[(8 * ks + lr) * 72 + 8 * j + lq];
                bhi[1] = sKhi[(8 * ks + 4 + lr) * 72 + 8 * j + lq];
                blo[1] = sKlo[(8 * ks + 4 + lr) * 72 + 8 * j + lq];
                mma_bf16(sacc[j], qhi[ks], bhi);
                mma_bf16(sacc[j], qlo[ks], bhi);
                mma_bf16(sacc[j], qhi[ks], blo);
            }
        }

        float mxA = -1e30f, mxB = -1e30f;
#pragma unroll
        for (int j = 0; j < 8; j++) {
#pragma unroll
            for (int cc = 0; cc < 2; cc++) {
                int sl = 8 * j + 2 * lr + cc;
                int sc = s0 + sl;
                float msv = sMs[sl];
                bool colOOB = (sc >= T_);
                {
                    float v = sacc[j][cc] * scale;
                    int jj = sc - rA + 4;
                    bool inb = (jj >= 0 && jj < 9);
                    if (inb) v += rlb[tlA * 9 + jj];
                    if (mtA == 0.f || msv == 0.f) v = -10000.0f;
                    if (colOOB) v = -1e30f;
                    if (inb) bnd[tlA * 9 + jj] = v;
                    sacc[j][cc] = v;
                    mxA = fmaxf(mxA, v);
                }
                {
                    float v = sacc[j][cc + 2] * scale;
                    int jj = sc - rB + 4;
                    bool inb = (jj >= 0 && jj < 9);
                    if (inb) v += rlb[tlB * 9 + jj];
                    if (mtB == 0.f || msv == 0.f) v = -10000.0f;
                    if (colOOB) v = -1e30f;
                    if (inb) bnd[tlB * 9 + jj] = v;
                    sacc[j][cc + 2] = v;
                    mxB = fmaxf(mxB, v);
                }
            }
        }
        mxA = fmaxf(mxA, __shfl_xor_sync(0xffffffffu, mxA, 1));
        mxA = fmaxf(mxA, __shfl_xor_sync(0xffffffffu, mxA, 2));
        mxB = fmaxf(mxB, __shfl_xor_sync(0xffffffffu, mxB, 1));
        mxB = fmaxf(mxB, __shfl_xor_sync(0xffffffffu, mxB, 2));
        float mnA = fmaxf(mA, mxA), mnB = fmaxf(mB, mxB);
        float rsA = __expf(mA - mnA), rsB = __expf(mB - mnB);
        mA = mnA; mB = mnB;
        float sumA = 0.f, sumB = 0.f;
#pragma unroll
        for (int j = 0; j < 8; j++) {
            sacc[j][0] = __expf(sacc[j][0] - mnA); sumA += sacc[j][0];
            sacc[j][1] = __expf(sacc[j][1] - mnA); sumA += sacc[j][1];
            sacc[j][2] = __expf(sacc[j][2] - mnB); sumB += sacc[j][2];
            sacc[j][3] = __expf(sacc[j][3] - mnB); sumB += sacc[j][3];
        }
        sumA += __shfl_xor_sync(0xffffffffu, sumA, 1);
        sumA += __shfl_xor_sync(0xffffffffu, sumA, 2);
        sumB += __shfl_xor_sync(0xffffffffu, sumB, 1);
        sumB += __shfl_xor_sync(0xffffffffu, sumB, 2);
        lA = lA * rsA + sumA;
        lB = lB * rsB + sumB;
#pragma unroll
        for (int n = 0; n < 8; n++) {
            oacc[n][0] *= rsA; oacc[n][1] *= rsA;
            oacc[n][2] *= rsB; oacc[n][3] *= rsB;
        }

#pragma unroll
        for (int ks = 0; ks < 4; ks++) {
            uint32_t phi[4], plo[4];
            split_pack(sacc[2 * ks][0],     sacc[2 * ks][1],     phi[0], plo[0]);
            split_pack(sacc[2 * ks][2],     sacc[2 * ks][3],     phi[1], plo[1]);
            split_pack(sacc[2 * ks + 1][0], sacc[2 * ks + 1][1], phi[2], plo[2]);
            split_pack(sacc[2 * ks + 1][2], sacc[2 * ks + 1][3], phi[3], plo[3]);
#pragma unroll
            for (int n = 0; n < 8; n++) {
                uint32_t bhi[2], blo[2];
                bhi[0] = sVhi[(8 * n + lq) * 36 + 8 * ks + lr];
                blo[0] = sVlo[(8 * n + lq) * 36 + 8 * ks + lr];
                bhi[1] = sVhi[(8 * n + lq) * 36 + 8 * ks + 4 + lr];
                blo[1] = sVlo[(8 * n + lq) * 36 + 8 * ks + 4 + lr];
                mma_bf16(oacc[n], phi, bhi);
                mma_bf16(oacc[n], plo, bhi);
                mma_bf16(oacc[n], phi, blo);
            }
        }
    }

    if (lr == 0) {
        sM[tlA] = mA; sL[tlA] = lA;
        sM[tlB] = mB; sL[tlB] = lB;
    }
    __syncthreads();
    for (int i = tid; i < 576; i += 128) {
        int t = i / 9;
        bnd[i] = __expf(bnd[i] - sM[t]) / sL[t];
    }
    __syncthreads();
    float* sT = (float*)sU;
    float invA = 1.f / lA, invB = 1.f / lB;
#pragma unroll
    for (int n = 0; n < 8; n++) {
#pragma unroll
        for (int cc = 0; cc < 2; cc++) {
            int d = 8 * n + 2 * lr + cc;
            float bA = 0.f, bB = 0.f;
#pragma unroll
            for (int j = 0; j < 9; j++) {
                float e = evs[j * 64 + d];
                bA += bnd[tlA * 9 + j] * e;
                bB += bnd[tlB * 9 + j] * e;
            }
            sT[d * 65 + tlA] = oacc[n][cc] * invA + bA;
            sT[d * 65 + tlB] = oacc[n][cc + 2] * invB + bB;
        }
    }
    __syncthreads();
    for (int i = tid; i < 64 * 64; i += 128) {
        int tl = i & 63, d = i >> 6;
        int t = t0 + tl;
        if (t < T_) Ob[(size_t)d * T_ + t] = sT[d * 65 + tl];
    }
}

// ---------------------------------------------------------------------------
__global__ void ln_kernel(const float* __restrict__ Yadd, const float* __restrict__ g,
                          const float* __restrict__ be,
                          const float* __restrict__ xm, uint32_t* __restrict__ xsplit) {
    const int b = blockIdx.y;
    const int tx = threadIdx.x;
    const int ty = threadIdx.y;
    const int t = blockIdx.x * 32 + tx;
    __shared__ float r1[8][32], r2[8][32];
    __shared__ float mu[32], wv[32];
    float s1 = 0.f, s2 = 0.f;
    if (t < T_) {
        for (int c = ty; c < H_; c += 8) {
            size_t off = (size_t)b * H_ * T_ + (size_t)c * T_ + t;
            float v = g_h[off] + Yadd[off];
            s1 += v; s2 += v * v;
        }
    }
    r1[ty][tx] = s1; r2[ty][tx] = s2;
    __syncthreads();
    if (ty == 0) {
        float a1 = 0.f, a2 = 0.f;
#pragma unroll
        for (int i = 0; i < 8; i++) { a1 += r1[i][tx]; a2 += r2[i][tx]; }
        float m = a1 / H_;
        float var = a2 / H_ - m * m;
        mu[tx] = m;
        wv[tx] = rsqrtf(var + 1e-5f);
    }
    __syncthreads();
    if (t < T_) {
        float m = mu[tx], ww = wv[tx];
        float mk = (xsplit != nullptr) ? xm[b * T_ + t] : 0.f;
        for (int c = ty; c < H_; c += 8) {
            size_t off = (size_t)b * H_ * T_ + (size_t)c * T_ + t;
            float v = g_h[off] + Yadd[off];
            float o = (v - m) * ww * g[c] + be[c];
            g_h[off] = o;
            if (xsplit != nullptr)
                xsplit[(size_t)((size_t)b * H_ + c) * T2_ + t + 1] = pack_elem(o * mk);
        }
    }
}

// ---------------------------------------------------------------------------
__global__ void finalize_kernel(const float* __restrict__ prior, const float* __restrict__ xm,
                                float* __restrict__ out) {
    int idx = blockIdx.x * blockDim.x + threadIdx.x;
    const int total = B_ * 2 * H_ * T_;
    if (idx >= total) return;
    int t = idx % T_;
    int o = (idx / T_) % (2 * H_);
    int b = idx / (2 * H_ * T_);
    float v = prior[idx] * xm[b * T_ + t];
    size_t dst = (size_t)(o < H_ ? 0 : BHT_) + (size_t)b * H_ * T_ + (size_t)(o & (H_ - 1)) * T_ + t;
    out[dst] = v;
}

// ---------------------------------------------------------------------------
extern "C" void kernel_launch(void* const* d_in, const int* in_sizes, int n_in,
                              void* d_out, int out_size) {
    const float* x   = (const float*)d_in[0];
    const float* xm  = (const float*)d_in[1];
    const float* Wq  = (const float*)d_in[2];
    const float* bq  = (const float*)d_in[3];
    const float* Wk  = (const float*)d_in[4];
    const float* bk  = (const float*)d_in[5];
    const float* Wv  = (const float*)d_in[6];
    const float* bv  = (const float*)d_in[7];
    const float* Wo  = (const float*)d_in[8];
    const float* bo  = (const float*)d_in[9];
    const float* ek  = (const float*)d_in[10];
    const float* ev  = (const float*)d_in[11];
    const float* g1  = (const float*)d_in[12];
    const float* b1  = (const float*)d_in[13];
    const float* g2  = (const float*)d_in[14];
    const float* b2  = (const float*)d_in[15];
    const float* Wf1 = (const float*)d_in[16];
    const float* bf1 = (const float*)d_in[17];
    const float* Wf2 = (const float*)d_in[18];
    const float* bf2 = (const float*)d_in[19];
    const float* Wp  = (const float*)d_in[20];
    const float* bp  = (const float*)d_in[21];
    float* out = (float*)d_out;

    float *ph, *pq, *pk, *pv, *patt, *py, *pff;
    uint32_t *pW1h, *pW1l, *pW2h, *pW2l, *pXa, *pXf;
    uint32_t *pWqh, *pWql, *pWkh, *pWkl, *pWvh, *pWvl, *pWoh, *pWol, *pWph, *pWpl;
    cudaGetSymbolAddress((void**)&ph,  g_h);
    cudaGetSymbolAddress((void**)&pq,  g_q);
    cudaGetSymbolAddress((void**)&pk,  g_k);
    cudaGetSymbolAddress((void**)&pv,  g_v);
    cudaGetSymbolAddress((void**)&patt, g_att);
    cudaGetSymbolAddress((void**)&py,  g_y);
    cudaGetSymbolAddress((void**)&pff, g_ff);
    cudaGetSymbolAddress((void**)&pW1h, gW1hi);
    cudaGetSymbolAddress((void**)&pW1l, gW1lo);
    cudaGetSymbolAddress((void**)&pW2h, gW2hi);
    cudaGetSymbolAddress((void**)&pW2l, gW2lo);
    cudaGetSymbolAddress((void**)&pWqh, gWqh);
    cudaGetSymbolAddress((void**)&pWql, gWql);
    cudaGetSymbolAddress((void**)&pWkh, gWkh);
    cudaGetSymbolAddress((void**)&pWkl, gWkl);
    cudaGetSymbolAddress((void**)&pWvh, gWvh);
    cudaGetSymbolAddress((void**)&pWvl, gWvl);
    cudaGetSymbolAddress((void**)&pWoh, gWoh);
    cudaGetSymbolAddress((void**)&pWol, gWol);
    cudaGetSymbolAddress((void**)&pWph, gWph);
    cudaGetSymbolAddress((void**)&pWpl, gWpl);
    cudaGetSymbolAddress((void**)&pXa, gXa);
    cudaGetSymbolAddress((void**)&pXf, gXf);

    cudaFuncSetAttribute(gemm_tc_kernel,  cudaFuncAttributeMaxDynamicSharedMemorySize, GEMM_DSM);
    cudaFuncSetAttribute(gemm3_tc_kernel, cudaFuncAttributeMaxDynamicSharedMemorySize, GEMM_DSM);
    cudaFuncSetAttribute(conv_tc_kernel,  cudaFuncAttributeMaxDynamicSharedMemorySize, CONV_DSM);

    const float scale = 0.125f;
    const int TT = (T_ + 63) / 64;       // 13
    const int TB32 = (T_ + 31) / 32;     // 25

    presplit_w_kernel<<<(W1P_ + 255) / 256, 256>>>(Wf1, pW1h, pW1l, W1P_);
    presplit_w_kernel<<<(W2P_ + 255) / 256, 256>>>(Wf2, pW2h, pW2l, W2P_);
    presplit_w_kernel<<<(WQP_ + 255) / 256, 256>>>(Wq, pWqh, pWql, WQP_);
    presplit_w_kernel<<<(WQP_ + 255) / 256, 256>>>(Wk, pWkh, pWkl, WQP_);
    presplit_w_kernel<<<(WQP_ + 255) / 256, 256>>>(Wv, pWvh, pWvl, WQP_);
    presplit_w_kernel<<<(WQP_ + 255) / 256, 256>>>(Wo, pWoh, pWol, WQP_);
    presplit_w_kernel<<<(WPP_ + 255) / 256, 256>>>(Wp, pWph, pWpl, WPP_);
    zero_pads_kernel<<<(B_ * FF_ * T2_ + 255) / 256, 256>>>();
    init_h_kernel<<<(BHT_ + 255) / 256, 256>>>(x, xm);

    const size_t WL = (size_t)H_ * H_ / 2;

    for (int L = 0; L < NL_; L++) {
        const float* ekL = ek + (size_t)L * 9 * HEAD_;
        const float* evL = ev + (size_t)L * 9 * HEAD_;

        gemm3_tc_kernel<<<dim3(TT, 12, B_), 256, GEMM_DSM>>>(
            pWqh + L * WL, pWql + L * WL, bq + L * H_, pq,
            pWkh + L * WL, pWkl + L * WL, bk + L * H_, pk,
            pWvh + L * WL, pWvl + L * WL, bv + L * H_, pv, ph);

        relk_kernel<<<(B_ * NH_ * T_ * 32 + 127) / 128, 128>>>(ekL, scale);
        attn_fused_kernel<<<dim3(TT, B_ * NH_), 128>>>(xm, scale, evL);

        gemm_tc_kernel<<<dim3(TT, H_ / 128, B_), 256, GEMM_DSM>>>(
            pWoh + L * WL, pWol + L * WL, bo + L * H_, patt, pq, H_, H_);
        ln_kernel<<<dim3(TB32, B_), dim3(32, 8)>>>(pq, g1 + L * H_, b1 + L * H_, xm, pXa);

        conv_tc_kernel<<<dim3(TT, FF_ / 128, B_), 256, CONV_DSM>>>(
            pW1h + (size_t)L * FF_ * (H_ * 3 / 2), pW1l + (size_t)L * FF_ * (H_ * 3 / 2),
            bf1 + L * FF_, pXa, nullptr, pXf, xm, FF_, H_, 1);
        conv_tc_kernel<<<dim3(TT, H_ / 128, B_), 256, CONV_DSM>>>(
            pW2h + (size_t)L * H_ * (FF_ * 3 / 2), pW2l + (size_t)L * H_ * (FF_ * 3 / 2),
            bf2 + L * H_, pXf, py, nullptr, xm, H_, FF_, 0);
        ln_kernel<<<dim3(TB32, B_), dim3(32, 8)>>>(py, g2 + L * H_, b2 + L * H_, xm, nullptr);
    }

    maskh_kernel<<<(BHT_ + 255) / 256, 256>>>(xm);
    gemm_tc_kernel<<<dim3(TT, 2 * H_ / 128, B_), 256, GEMM_DSM>>>(pWph, pWpl, bp, ph, pff, 2 * H_, H_);
    finalize_kernel<<<(B_ * 2 * H_ * T_ + 255) / 256, 256>>>(pff, xm, out);
}